// round 14
// baseline (speedup 1.0000x reference)
#include <cuda_runtime.h>
#include <cuda_fp16.h>
#include <cstdint>
#include <math.h>

#define BATCH 2048
#define FEW 5
#define NBR 200
#define ED 128
#define DM 256
#define DI 512
#define LH 512
#define G4 2048          // 4*LSTM_HIDDEN
#define NSYM 200001
#define NITEMS (2*BATCH + 2*FEW)   // 4106
#define NROWS_SE (BATCH + FEW)     // 2053
#define MPAD_S 4224      // NITEMS padded to 128
#define MPAD_X 2176      // NROWS_SE padded to 128

// ================= scratch (device globals; zero-initialized) =========
__device__ float g_qg[(size_t)BATCH * DM];      // query_g (fp32, LSTM residual)
__device__ float g_sgrows[(size_t)FEW * DM];    // support rows post encoder
__device__ float g_sg[DM];                      // mean support
__device__ float g_spartp[G4];                  // permuted sg @ w_hh[:,256:].T
__device__ float g_bsump[G4];                   // permuted b_ih + b_hh
__device__ float g_xwp[(size_t)BATCH * G4];     // permuted q@w_ih.T + biases
__device__ float g_h[(size_t)BATCH * DM];       // h (256-dim)
__device__ float g_c[(size_t)BATCH * LH];       // cell state
__device__ float g_deg[MPAD_S];                 // degrees per item

// fp16 operands (single-term)
__device__ __half g_EmbH[(size_t)NSYM * ED];   // fp16 embedding table
__device__ __half g_Sh[(size_t)MPAD_S * DM];   // neighbor sums
__device__ __half g_Xh[(size_t)MPAD_X * DM];   // concat tanh output
__device__ float  g_X32[(size_t)MPAD_X * DM];  // fp32 X (residual)
__device__ __half g_Hh[(size_t)MPAD_X * DI];   // relu hidden
__device__ float  g_out32[(size_t)MPAD_X * DM];// pre-LN output
__device__ __half g_A0h[(size_t)BATCH * DM];   // LSTM A ping-pong buffers
__device__ __half g_A1h[(size_t)BATCH * DM];
__device__ __half g_Bih[(size_t)G4 * DM];      // permuted weights (fp16)
__device__ __half g_Bhh[(size_t)G4 * DM];
__device__ __half g_Wg[(size_t)ED * DM];
__device__ __half g_W1[(size_t)DI * DM];
__device__ __half g_W2[(size_t)DM * DI];

__device__ __forceinline__ float sigmoidf(float x) { return 1.f / (1.f + __expf(-x)); }
__device__ __forceinline__ uint32_t smem_u32(const void* p) {
    uint32_t a;
    asm("{ .reg .u64 tmp; cvta.to.shared.u64 tmp, %1; cvt.u32.u64 %0, tmp; }"
        : "=r"(a) : "l"(p));
    return a;
}
__device__ __forceinline__ void ldmx4(uint32_t addr, uint32_t& r0, uint32_t& r1,
                                      uint32_t& r2, uint32_t& r3) {
    asm volatile("ldmatrix.sync.aligned.m8n8.x4.shared.b16 {%0,%1,%2,%3}, [%4];"
        : "=r"(r0), "=r"(r1), "=r"(r2), "=r"(r3) : "r"(addr));
}
__device__ __forceinline__ void cpa16(uint32_t s, const void* g) {
    asm volatile("cp.async.cg.shared.global [%0], [%1], 16;" :: "r"(s), "l"(g));
}
#define CP_COMMIT() asm volatile("cp.async.commit_group;" ::: "memory")
#define CP_WAIT(n)  asm volatile("cp.async.wait_group %0;" :: "n"(n) : "memory")

#define MMA(acc, a, b0, b1) \
    asm volatile( \
        "mma.sync.aligned.m16n8k16.row.col.f32.f16.f16.f32 " \
        "{%0,%1,%2,%3}, {%4,%5,%6,%7}, {%8,%9}, {%0,%1,%2,%3};" \
        : "+f"((acc)[0]), "+f"((acc)[1]), "+f"((acc)[2]), "+f"((acc)[3]) \
        : "r"((a)[0]), "r"((a)[1]), "r"((a)[2]), "r"((a)[3]), \
          "r"(b0), "r"(b1))

// ---------------- conversion helpers ----------------
__device__ __forceinline__ void conv_halfB(const float* W, int ld, int blk, int t,
                                           __half* bh)
{
    int idx = blk * 256 + t;                      // 2048*64 groups of 4
    int row = idx >> 6, c4 = (idx & 63) << 2;
    int rp = 4 * (row & 511) + (row >> 9);        // gate permutation
    float4 v = *(const float4*)(W + (size_t)row * ld + c4);
    __half2 h01, h23;
    h01.x = __float2half_rn(v.x); h01.y = __float2half_rn(v.y);
    h23.x = __float2half_rn(v.z); h23.y = __float2half_rn(v.w);
    __half2* dh = (__half2*)(bh + (size_t)rp * DM + c4);
    dh[0] = h01; dh[1] = h23;
}
__device__ __forceinline__ void conv_halfW(const float* W, int blk, int t, __half* bh)
{
    int idx = blk * 256 + t;
    int c4 = idx << 2;
    float4 v = *(const float4*)(W + c4);
    __half2 h01, h23;
    h01.x = __float2half_rn(v.x); h01.y = __float2half_rn(v.y);
    h23.x = __float2half_rn(v.z); h23.y = __float2half_rn(v.w);
    *(__half2*)(bh + c4)     = h01;
    *(__half2*)(bh + c4 + 2) = h23;
}

// ---------------- K_convEmb: fp32 embedding table -> fp16 (25001 blocks) -------
__global__ __launch_bounds__(256) void k_convEmb(const float* __restrict__ emb)
{
    int idx = blockIdx.x * 256 + threadIdx.x;
    size_t c4 = (size_t)idx << 2;
    if (c4 + 3 >= (size_t)NSYM * ED) {
        for (size_t c = c4; c < (size_t)NSYM * ED; c++)
            g_EmbH[c] = __float2half_rn(emb[c]);
        return;
    }
    float4 v = *(const float4*)(emb + c4);
    __half2 h01, h23;
    h01.x = __float2half_rn(v.x); h01.y = __float2half_rn(v.y);
    h23.x = __float2half_rn(v.z); h23.y = __float2half_rn(v.w);
    *(__half2*)(g_EmbH + c4)     = h01;
    *(__half2*)(g_EmbH + c4 + 2) = h23;
}

// ---------------- K0: all weight conversions in one launch (1312 blocks) -------
__global__ __launch_bounds__(256) void k_convAll(
    const float* __restrict__ wih, const float* __restrict__ whh,
    const float* __restrict__ gcnw, const float* __restrict__ p1w,
    const float* __restrict__ p2w)
{
    int b = blockIdx.x, t = threadIdx.x;
    if (b < 512)        conv_halfB(wih, DM, b, t, g_Bih);
    else if (b < 1024)  conv_halfB(whh, LH, b - 512, t, g_Bhh);
    else if (b < 1056)  conv_halfW(gcnw, b - 1024, t, g_Wg);
    else if (b < 1184)  conv_halfW(p1w, b - 1056, t, g_W1);
    else                conv_halfW(p2w, b - 1184, t, g_W2);
}

// ---------------- K1: gather + sum over neighbors (fp16 table, warp-split-k) ----
__global__ __launch_bounds__(256) void k_gather(
    const int* __restrict__ qlc, const int* __restrict__ qrc,
    const int* __restrict__ slc, const int* __restrict__ src_,
    const float* __restrict__ qld, const float* __restrict__ qrd,
    const float* __restrict__ sld, const float* __restrict__ srd)
{
    __shared__ int ids[NBR * 2];
    __shared__ float red[8][128];
    int b = blockIdx.x;
    const int* conn; const float* degp; int row;
    if (b < BATCH)               { conn = qlc;  degp = qld; row = b; }
    else if (b < 2*BATCH)        { conn = qrc;  degp = qrd; row = b - BATCH; }
    else if (b < 2*BATCH + FEW)  { conn = slc;  degp = sld; row = b - 2*BATCH; }
    else                         { conn = src_; degp = srd; row = b - 2*BATCH - FEW; }
    const int* p = conn + (size_t)row * NBR * 2;
    int t = threadIdx.x;
    for (int i = t; i < NBR * 2; i += 256) ids[i] = p[i];
    if (t == 0) g_deg[b] = degp[row];
    __syncthreads();

    int w = t >> 5, lane = t & 31;
    int side = w >> 2;        // 0 = rel, 1 = ent
    int ks = w & 3;
    float4 acc = make_float4(0.f, 0.f, 0.f, 0.f);
    #pragma unroll 2
    for (int k = ks; k < NBR; k += 4) {
        int id = ids[2 * k + side];
        uint2 v = __ldg((const uint2*)(g_EmbH + (size_t)id * ED) + lane);
        __half2 h01 = *(__half2*)&v.x;
        __half2 h23 = *(__half2*)&v.y;
        acc.x += __half2float(h01.x); acc.y += __half2float(h01.y);
        acc.z += __half2float(h23.x); acc.w += __half2float(h23.y);
    }
    *(float4*)&red[w][lane * 4] = acc;
    __syncthreads();

    int s2 = t >> 7, col = t & 127;
    float a = red[s2 * 4 + 0][col] + red[s2 * 4 + 1][col]
            + red[s2 * 4 + 2][col] + red[s2 * 4 + 3][col];
    g_Sh[(size_t)b * DM + t] = __float2half_rn(a);
}

// ---------------- generic HMMA GEMM: C[M,N] = A[M,K] @ B[N,K]^T ----------------
// fp16 single-term GEMM, 64-wide k-chunks (144 B padded rows -> conflict-free
// ldmatrix), cp.async pipeline, templated epilogues.
// MI = m-frags per warp (1 -> 64-row CTA tile, 2 -> 128-row).
#define ROWB 144                  // 128 B data + 16 B pad per k64 row
#define HSTG(MI) ((64 * (MI) + 128) * ROWB)
#define HSTAGES(MI) ((MI) == 2 ? 3 : 4)
#define HSM(MI) (HSTAGES(MI) * HSTG(MI))

template<int MODE, int KTILES, int MI>
__global__ __launch_bounds__(256, 2) void k_hmma(
    const __half* __restrict__ Ah, const __half* __restrict__ Bh,
    const float* __restrict__ e0, __half* __restrict__ Aout_h)
{
    constexpr int K = KTILES * 32;
    constexpr int nchunks = KTILES / 2;      // 64-wide chunks
    constexpr int TM = 64 * MI;
    constexpr int SN = HSTAGES(MI);
    constexpr int STG = HSTG(MI);
    constexpr int offBh = TM * ROWB;

    extern __shared__ char smem[];
    uint32_t sBase = smem_u32(smem);

    int tid = threadIdx.x, lane = tid & 31, w = tid >> 5;
    int m0 = blockIdx.y * TM, n0 = blockIdx.x * 128;
    int wm = w >> 1, wn = w & 1;

    // A load: MI==2: row=tid>>1 (0..127), 4 segs at (tid&1)*64B.
    //         MI==1: row=tid>>2 (0..63), 2 segs at (tid&3)*32B.
    int aRow = (MI == 2) ? (tid >> 1) : (tid >> 2);
    int aOffB = (MI == 2) ? ((tid & 1) * 64) : ((tid & 3) * 32);
    int bRow = tid >> 1;
    int bOffB = (tid & 1) * 64;

    uint32_t aFragOff = (uint32_t)(lane & 15) * ROWB + ((lane >> 4) * 16)
                      + (uint32_t)(wm * 16 * MI) * ROWB;
    uint32_t bFragOff = (uint32_t)((lane & 7) + ((lane >> 4) * 8)) * ROWB
                      + (((lane >> 3) & 1) * 16)
                      + (uint32_t)(wn * 64) * ROWB;

    uint32_t aDst = (uint32_t)aRow * ROWB + aOffB;
    uint32_t bDst = (uint32_t)bRow * ROWB + bOffB;

    float acc[MI][8][4];
    #pragma unroll
    for (int i = 0; i < MI; i++)
        #pragma unroll
        for (int j = 0; j < 8; j++)
            #pragma unroll
            for (int e = 0; e < 4; e++) acc[i][j][e] = 0.f;

    auto issue = [&](int slot, int chunk) {
        int kc = chunk * 64;
        uint32_t st = sBase + slot * STG;
        const __half* Aph = Ah + (size_t)(m0 + aRow) * K + kc + (aOffB >> 1);
        const __half* Bph = Bh + (size_t)(n0 + bRow) * K + kc + (bOffB >> 1);
        if (MI == 2) {
            cpa16(st + aDst,      Aph);
            cpa16(st + aDst + 16, Aph + 8);
            cpa16(st + aDst + 32, Aph + 16);
            cpa16(st + aDst + 48, Aph + 24);
        } else {
            cpa16(st + aDst,      Aph);
            cpa16(st + aDst + 16, Aph + 8);
        }
        cpa16(st + offBh + bDst,      Bph);
        cpa16(st + offBh + bDst + 16, Bph + 8);
        cpa16(st + offBh + bDst + 32, Bph + 16);
        cpa16(st + offBh + bDst + 48, Bph + 24);
    };

    // prologue: stages 0..SN-2
    #pragma unroll
    for (int s = 0; s < SN - 1 && s < nchunks; s++) { issue(s, s); CP_COMMIT(); }

    #pragma unroll 1
    for (int it = 0; it < nchunks; it++) {
        CP_WAIT(SN - 2);
        __syncthreads();
        int nxt = it + SN - 1;
        if (nxt < nchunks) issue(nxt % SN, nxt);
        CP_COMMIT();

        uint32_t st = sBase + (it % SN) * STG;
        #pragma unroll
        for (int ks = 0; ks < 4; ks++) {
            uint32_t abH = st + aFragOff + ks * 32;
            uint32_t bbH = st + offBh + bFragOff + ks * 32;

            uint32_t afr[MI][4];
            ldmx4(abH, afr[0][0], afr[0][1], afr[0][2], afr[0][3]);
            if (MI == 2)
                ldmx4(abH + 16 * ROWB, afr[MI-1][0], afr[MI-1][1], afr[MI-1][2], afr[MI-1][3]);

            uint32_t bfrH[8][2];
            #pragma unroll
            for (int q = 0; q < 4; q++)
                ldmx4(bbH + q * 16 * ROWB,
                      bfrH[2*q][0], bfrH[2*q][1], bfrH[2*q+1][0], bfrH[2*q+1][1]);
            #pragma unroll
            for (int nj = 0; nj < 8; nj++)
                #pragma unroll
                for (int mi = 0; mi < MI; mi++)
                    MMA(acc[mi][nj], afr[mi], bfrH[nj][0], bfrH[nj][1]);
        }
    }

    // ---------------- epilogues ----------------
    if (MODE == 2) {
        #pragma unroll
        for (int mi = 0; mi < MI; mi++) {
            int r0 = m0 + wm * 16 * MI + mi * 16 + (lane >> 2);
            #pragma unroll
            for (int rr = 0; rr < 2; rr++) {
                int gb = r0 + rr * 8;
                if (gb >= NITEMS) continue;
                float dg = g_deg[gb];
                int r2, cb;
                if (gb < BATCH)                { r2 = gb;                         cb = 0; }
                else if (gb < 2*BATCH)         { r2 = gb - BATCH;                 cb = ED; }
                else if (gb < 2*BATCH + FEW)   { r2 = BATCH + gb - 2*BATCH;       cb = 0; }
                else                           { r2 = BATCH + gb - 2*BATCH - FEW; cb = ED; }
                #pragma unroll
                for (int nj = 0; nj < 8; nj++) {
                    int cc = n0 + wn * 64 + nj * 8 + ((lane & 3) << 1);  // 0..127
                    float v0 = tanhf((acc[mi][nj][rr * 2 + 0] + 200.f * e0[cc])     / dg);
                    float v1 = tanhf((acc[mi][nj][rr * 2 + 1] + 200.f * e0[cc + 1]) / dg);
                    size_t off = (size_t)r2 * DM + cb + cc;
                    g_X32[off] = v0; g_X32[off + 1] = v1;
                    g_Xh[off]     = __float2half_rn(v0);
                    g_Xh[off + 1] = __float2half_rn(v1);
                }
            }
        }
    } else if (MODE == 3) {
        #pragma unroll
        for (int mi = 0; mi < MI; mi++) {
            int r0 = m0 + wm * 16 * MI + mi * 16 + (lane >> 2);
            #pragma unroll
            for (int rr = 0; rr < 2; rr++) {
                int mr = r0 + rr * 8;
                #pragma unroll
                for (int nj = 0; nj < 8; nj++) {
                    int cc = n0 + wn * 64 + nj * 8 + ((lane & 3) << 1);
                    float v0 = fmaxf(acc[mi][nj][rr * 2 + 0] + e0[cc], 0.f);
                    float v1 = fmaxf(acc[mi][nj][rr * 2 + 1] + e0[cc + 1], 0.f);
                    size_t off = (size_t)mr * DI + cc;
                    g_Hh[off]     = __float2half_rn(v0);
                    g_Hh[off + 1] = __float2half_rn(v1);
                }
            }
        }
    } else if (MODE == 4) {
        #pragma unroll
        for (int mi = 0; mi < MI; mi++) {
            int r0 = m0 + wm * 16 * MI + mi * 16 + (lane >> 2);
            #pragma unroll
            for (int rr = 0; rr < 2; rr++) {
                int mr = r0 + rr * 8;
                #pragma unroll
                for (int nj = 0; nj < 8; nj++) {
                    int cc = n0 + wn * 64 + nj * 8 + ((lane & 3) << 1);
                    size_t off = (size_t)mr * DM + cc;
                    float2 xr = *(const float2*)(g_X32 + off);
                    float2 o;
                    o.x = acc[mi][nj][rr * 2 + 0] + e0[cc]     + xr.x;
                    o.y = acc[mi][nj][rr * 2 + 1] + e0[cc + 1] + xr.y;
                    *(float2*)(g_out32 + off) = o;
                }
            }
        }
    } else { // MODE 5 / 6: fused LSTM gates
        constexpr bool first = (MODE == 5);
        #pragma unroll
        for (int mi = 0; mi < MI; mi++) {
            int mr = m0 + wm * 16 * MI + mi * 16 + (lane >> 2);
            #pragma unroll
            for (int nj = 0; nj < 8; nj++) {
                int cc = n0 + wn * 64 + nj * 8 + ((lane & 3) << 1);
                float d0 = acc[mi][nj][0], d1 = acc[mi][nj][1];
                float d2 = acc[mi][nj][2], d3 = acc[mi][nj][3];
                if (first) {
                    float2 bsp = *(const float2*)(g_bsump + cc);
                    d0 += bsp.x; d1 += bsp.y; d2 += bsp.x; d3 += bsp.y;
                    float2 o0; o0.x = d0; o0.y = d1;
                    float2 o1; o1.x = d2; o1.y = d3;
                    *(float2*)(g_xwp + (size_t)mr * G4 + cc) = o0;
                    *(float2*)(g_xwp + (size_t)(mr + 8) * G4 + cc) = o1;
                } else {
                    float2 sp = *(const float2*)(g_spartp + cc);
                    float2 x0 = *(const float2*)(g_xwp + (size_t)mr * G4 + cc);
                    float2 x1 = *(const float2*)(g_xwp + (size_t)(mr + 8) * G4 + cc);
                    d0 += x0.x + sp.x; d1 += x0.y + sp.y;
                    d2 += x1.x + sp.x; d3 += x1.y + sp.y;
                }
                float p0 = __shfl_xor_sync(0xffffffffu, d0, 1);
                float p1 = __shfl_xor_sync(0xffffffffu, d1, 1);
                float p2 = __shfl_xor_sync(0xffffffffu, d2, 1);
                float p3 = __shfl_xor_sync(0xffffffffu, d3, 1);
                if (((lane & 3) & 1) == 0) {
                    int u = cc >> 2;     // unit index 0..511
                    float cp0 = first ? 0.f : g_c[(size_t)mr * LH + u];
                    float cn0 = sigmoidf(d1) * cp0 + sigmoidf(d0) * tanhf(p0);
                    g_c[(size_t)mr * LH + u] = cn0;
                    float cp1 = first ? 0.f : g_c[(size_t)(mr + 8) * LH + u];
                    float cn1 = sigmoidf(d3) * cp1 + sigmoidf(d2) * tanhf(p2);
                    g_c[(size_t)(mr + 8) * LH + u] = cn1;
                    if (u < DM) {
                        float h0 = g_qg[(size_t)mr * DM + u] + sigmoidf(p1) * tanhf(cn0);
                        float h1 = g_qg[(size_t)(mr + 8) * DM + u] + sigmoidf(p3) * tanhf(cn1);
                        g_h[(size_t)mr * DM + u] = h0;
                        g_h[(size_t)(mr + 8) * DM + u] = h1;
                        Aout_h[(size_t)mr * DM + u]       = __float2half_rn(h0);
                        Aout_h[(size_t)(mr + 8) * DM + u] = __float2half_rn(h1);
                    }
                }
            }
        }
    }
}

// ---------------- K_ln: LayerNorm (ddof=1) + scatter -------
__global__ __launch_bounds__(256) void k_ln(
    const float* __restrict__ lna, const float* __restrict__ lnb)
{
    int t = threadIdx.x;
    int warp = t >> 5, lane = t & 31;
    int gr = blockIdx.x * 8 + warp;
    if (gr >= NROWS_SE) return;
    const float* x = g_out32 + (size_t)gr * DM;
    float xs[8];
    float s = 0.f;
    #pragma unroll
    for (int i = 0; i < 8; i++) { xs[i] = x[lane + i * 32]; s += xs[i]; }
    #pragma unroll
    for (int o = 16; o; o >>= 1) s += __shfl_xor_sync(0xffffffffu, s, o);
    float mu = s * (1.f / 256.f);
    float v = 0.f;
    #pragma unroll
    for (int i = 0; i < 8; i++) { float d = xs[i] - mu; v += d * d; }
    #pragma unroll
    for (int o = 16; o; o >>= 1) v += __shfl_xor_sync(0xffffffffu, v, o);
    float sigma = sqrtf(v * (1.f / 255.f));
    float inv = 1.f / (sigma + 0.001f);
    if (gr < BATCH) {
        #pragma unroll
        for (int i = 0; i < 8; i++) {
            int c = lane + i * 32;
            float val = (xs[i] - mu) * inv * lna[c] + lnb[c];
            g_qg[(size_t)gr * DM + c] = val;
            g_A0h[(size_t)gr * DM + c] = __float2half_rn(val);
        }
    } else {
        float* dst = g_sgrows + (size_t)(gr - BATCH) * DM;
        #pragma unroll
        for (int i = 0; i < 8; i++) {
            int c = lane + i * 32;
            dst[c] = (xs[i] - mu) * inv * lna[c] + lnb[c];
        }
    }
}

// ---------------- K_prep: sg mean + permuted spart + permuted bias sum --------
__global__ __launch_bounds__(256) void k_prep(
    const float* __restrict__ whh, const float* __restrict__ bih,
    const float* __restrict__ bhh)
{
    __shared__ float sg_s[DM];
    int t = threadIdx.x;
    {
        float a = 0.f;
        #pragma unroll
        for (int r = 0; r < FEW; r++) a += g_sgrows[(size_t)r * DM + t];
        a *= (1.f / (float)FEW);
        sg_s[t] = a;
        if (blockIdx.x == 0) g_sg[t] = a;
    }
    __syncthreads();
    int r = blockIdx.x * 256 + t;        // original gate-major row 0..2047
    const float* wr = whh + (size_t)r * LH + DM;
    float a = 0.f;
    for (int c = 0; c < DM; c++) a += sg_s[c] * __ldg(wr + c);
    int rp = 4 * (r & 511) + (r >> 9);
    g_spartp[rp] = a;
    g_bsump[rp] = bih[r] + bhh[r];
}

// ---------------- K8: final scores out[n] = dot(h[n], sg) ----------------
__global__ __launch_bounds__(256) void k_score(float* __restrict__ out)
{
    __shared__ float sg_s[DM];
    int t = threadIdx.x;
    if (t < DM) sg_s[t] = g_sg[t];
    __syncthreads();
    int warp = t >> 5, lane = t & 31;
    int n = blockIdx.x * 8 + warp;
    const float* h = g_h + (size_t)n * DM;
    float a = 0.f;
    #pragma unroll
    for (int c = lane; c < DM; c += 32) a += h[c] * sg_s[c];
    #pragma unroll
    for (int o = 16; o; o >>= 1) a += __shfl_xor_sync(0xffffffffu, a, o);
    if (lane == 0) out[n] = a;
}

// ---------------- launch ----------------
extern "C" void kernel_launch(void* const* d_in, const int* in_sizes, int n_in,
                              void* d_out, int out_size)
{
    const int*   qlc  = (const int*)  d_in[0];
    const float* qld  = (const float*)d_in[1];
    const int*   qrc  = (const int*)  d_in[2];
    const float* qrd  = (const float*)d_in[3];
    const int*   slc  = (const int*)  d_in[4];
    const float* sld  = (const float*)d_in[5];
    const int*   src_ = (const int*)  d_in[6];
    const float* srd  = (const float*)d_in[7];
    const float* emb  = (const float*)d_in[8];
    const float* gcnw = (const float*)d_in[9];
    const float* gcnb = (const float*)d_in[10];
    const float* p1w  = (const float*)d_in[11];
    const float* p1b  = (const float*)d_in[12];
    const float* p2w  = (const float*)d_in[13];
    const float* p2b  = (const float*)d_in[14];
    const float* lna  = (const float*)d_in[15];
    const float* lnb  = (const float*)d_in[16];
    const float* wih  = (const float*)d_in[17];
    const float* whh  = (const float*)d_in[18];
    const float* bih  = (const float*)d_in[19];
    const float* bhh  = (const float*)d_in[20];
    float* out = (float*)d_out;

    __half *wg, *w1, *w2, *sh, *xh, *hh2, *a0h, *a1h, *bihp, *bhhp;
    cudaGetSymbolAddress((void**)&wg, g_Wg);
    cudaGetSymbolAddress((void**)&w1, g_W1);
    cudaGetSymbolAddress((void**)&w2, g_W2);
    cudaGetSymbolAddress((void**)&sh, g_Sh);
    cudaGetSymbolAddress((void**)&xh, g_Xh);
    cudaGetSymbolAddress((void**)&hh2, g_Hh);
    cudaGetSymbolAddress((void**)&a0h, g_A0h);
    cudaGetSymbolAddress((void**)&a1h, g_A1h);
    cudaGetSymbolAddress((void**)&bihp, g_Bih);
    cudaGetSymbolAddress((void**)&bhhp, g_Bhh);

    cudaFuncSetAttribute(k_hmma<2, 8, 1>,  cudaFuncAttributeMaxDynamicSharedMemorySize, HSM(1));
    cudaFuncSetAttribute(k_hmma<3, 8, 1>,  cudaFuncAttributeMaxDynamicSharedMemorySize, HSM(1));
    cudaFuncSetAttribute(k_hmma<4, 16, 1>, cudaFuncAttributeMaxDynamicSharedMemorySize, HSM(1));
    cudaFuncSetAttribute(k_hmma<5, 8, 2>,  cudaFuncAttributeMaxDynamicSharedMemorySize, HSM(2));
    cudaFuncSetAttribute(k_hmma<6, 8, 2>,  cudaFuncAttributeMaxDynamicSharedMemorySize, HSM(2));

    // 0: embedding table -> fp16
    k_convEmb<<<25001, 256>>>(emb);
    // 1: weight conversions
    k_convAll<<<1312, 256>>>(wih, whh, gcnw, p1w, p2w);
    // 2: gather (fp16 table)
    k_gather<<<NITEMS, 256>>>(qlc, qrc, slc, src_, qld, qrd, sld, srd);
    // 3: GCN as GEMM (ncu captures this)
    k_hmma<2, 8, 1><<<dim3(1, MPAD_S / 64), 256, HSM(1)>>>(sh, wg, gcnb, nullptr);
    // 4: mlp1
    k_hmma<3, 8, 1><<<dim3(4, MPAD_X / 64), 256, HSM(1)>>>(xh, w1, p1b, nullptr);
    // 5: mlp2
    k_hmma<4, 16, 1><<<dim3(2, MPAD_X / 64), 256, HSM(1)>>>(hh2, w2, p2b, nullptr);
    k_ln<<<(NROWS_SE + 7) / 8, 256>>>(lna, lnb);
    k_prep<<<G4 / 256, 256>>>(whh, bih, bhh);

    // LSTM steps with fused gate epilogues (A ping-pong A0 -> A1 -> A0 -> ...)
    k_hmma<5, 8, 2><<<dim3(16, 16), 256, HSM(2)>>>(a0h, bihp, nullptr, a1h);
    k_hmma<6, 8, 2><<<dim3(16, 16), 256, HSM(2)>>>(a1h, bhhp, nullptr, a0h);
    k_hmma<6, 8, 2><<<dim3(16, 16), 256, HSM(2)>>>(a0h, bhhp, nullptr, a1h);
    k_hmma<6, 8, 2><<<dim3(16, 16), 256, HSM(2)>>>(a1h, bhhp, nullptr, a0h);
    k_score<<<BATCH / 8, 256>>>(out);
}

// round 15
// speedup vs baseline: 1.0062x; 1.0062x over previous
#include <cuda_runtime.h>
#include <cuda_fp16.h>
#include <cstdint>
#include <math.h>

#define BATCH 2048
#define FEW 5
#define NBR 200
#define ED 128
#define DM 256
#define DI 512
#define LH 512
#define G4 2048          // 4*LSTM_HIDDEN
#define NSYM 200001
#define NITEMS (2*BATCH + 2*FEW)   // 4106
#define NROWS_SE (BATCH + FEW)     // 2053
#define MPAD_S 4224      // NITEMS padded to 128
#define MPAD_X 2176      // NROWS_SE padded to 128

// ================= scratch (device globals; zero-initialized) =========
__device__ float g_qg[(size_t)BATCH * DM];      // query_g (fp32, LSTM residual)
__device__ float g_sgrows[(size_t)FEW * DM];    // support rows post encoder
__device__ float g_sg[DM];                      // mean support
__device__ float g_spartp[G4];                  // permuted sg @ w_hh[:,256:].T
__device__ float g_bsump[G4];                   // permuted b_ih + b_hh
__device__ float g_xwp[(size_t)BATCH * G4];     // permuted q@w_ih.T + biases
__device__ float g_h[(size_t)BATCH * DM];       // h (256-dim)
__device__ float g_c[(size_t)BATCH * LH];       // cell state
__device__ float g_deg[MPAD_S];                 // degrees per item

// fp16 operands (single-term)
__device__ __half g_EmbH[(size_t)NSYM * ED];   // fp16 embedding table
__device__ __half g_Sh[(size_t)MPAD_S * DM];   // neighbor sums
__device__ __half g_Xh[(size_t)MPAD_X * DM];   // concat tanh output
__device__ float  g_X32[(size_t)MPAD_X * DM];  // fp32 X (residual)
__device__ __half g_Hh[(size_t)MPAD_X * DI];   // relu hidden
__device__ float  g_out32[(size_t)MPAD_X * DM];// pre-LN output
__device__ __half g_A0h[(size_t)BATCH * DM];   // LSTM A ping-pong buffers
__device__ __half g_A1h[(size_t)BATCH * DM];
__device__ __half g_Bih[(size_t)G4 * DM];      // permuted weights (fp16)
__device__ __half g_Bhh[(size_t)G4 * DM];
__device__ __half g_Wg[(size_t)ED * DM];
__device__ __half g_W1[(size_t)DI * DM];
__device__ __half g_W2[(size_t)DM * DI];

__device__ __forceinline__ float sigmoidf(float x) { return 1.f / (1.f + __expf(-x)); }
__device__ __forceinline__ float fast_tanh(float x) {
    float ax = fabsf(x);
    float e = __expf(-2.f * ax);
    float r = (1.f - e) / (1.f + e);
    return copysignf(r, x);
}
__device__ __forceinline__ uint32_t smem_u32(const void* p) {
    uint32_t a;
    asm("{ .reg .u64 tmp; cvta.to.shared.u64 tmp, %1; cvt.u32.u64 %0, tmp; }"
        : "=r"(a) : "l"(p));
    return a;
}
__device__ __forceinline__ void ldmx4(uint32_t addr, uint32_t& r0, uint32_t& r1,
                                      uint32_t& r2, uint32_t& r3) {
    asm volatile("ldmatrix.sync.aligned.m8n8.x4.shared.b16 {%0,%1,%2,%3}, [%4];"
        : "=r"(r0), "=r"(r1), "=r"(r2), "=r"(r3) : "r"(addr));
}
__device__ __forceinline__ void cpa16(uint32_t s, const void* g) {
    asm volatile("cp.async.cg.shared.global [%0], [%1], 16;" :: "r"(s), "l"(g));
}
#define CP_COMMIT() asm volatile("cp.async.commit_group;" ::: "memory")
#define CP_WAIT(n)  asm volatile("cp.async.wait_group %0;" :: "n"(n) : "memory")

#define MMA(acc, a, b0, b1) \
    asm volatile( \
        "mma.sync.aligned.m16n8k16.row.col.f32.f16.f16.f32 " \
        "{%0,%1,%2,%3}, {%4,%5,%6,%7}, {%8,%9}, {%0,%1,%2,%3};" \
        : "+f"((acc)[0]), "+f"((acc)[1]), "+f"((acc)[2]), "+f"((acc)[3]) \
        : "r"((a)[0]), "r"((a)[1]), "r"((a)[2]), "r"((a)[3]), \
          "r"(b0), "r"(b1))

// ---------------- conversion helpers ----------------
__device__ __forceinline__ void conv_halfB(const float* W, int ld, int blk, int t,
                                           __half* bh)
{
    int idx = blk * 256 + t;                      // 2048*64 groups of 4
    int row = idx >> 6, c4 = (idx & 63) << 2;
    int rp = 4 * (row & 511) + (row >> 9);        // gate permutation
    float4 v = *(const float4*)(W + (size_t)row * ld + c4);
    __half2 h01, h23;
    h01.x = __float2half_rn(v.x); h01.y = __float2half_rn(v.y);
    h23.x = __float2half_rn(v.z); h23.y = __float2half_rn(v.w);
    __half2* dh = (__half2*)(bh + (size_t)rp * DM + c4);
    dh[0] = h01; dh[1] = h23;
}
__device__ __forceinline__ void conv_halfW(const float* W, int blk, int t, __half* bh)
{
    int idx = blk * 256 + t;
    int c4 = idx << 2;
    float4 v = *(const float4*)(W + c4);
    __half2 h01, h23;
    h01.x = __float2half_rn(v.x); h01.y = __float2half_rn(v.y);
    h23.x = __float2half_rn(v.z); h23.y = __float2half_rn(v.w);
    *(__half2*)(bh + c4)     = h01;
    *(__half2*)(bh + c4 + 2) = h23;
}

// ---------------- K0: ALL conversions (weights + embedding) in one launch -----
// blocks 0..1311: weights; blocks 1312..26312: embedding table
__global__ __launch_bounds__(256) void k_convAll(
    const float* __restrict__ wih, const float* __restrict__ whh,
    const float* __restrict__ gcnw, const float* __restrict__ p1w,
    const float* __restrict__ p2w, const float* __restrict__ emb)
{
    int b = blockIdx.x, t = threadIdx.x;
    if (b < 512)        conv_halfB(wih, DM, b, t, g_Bih);
    else if (b < 1024)  conv_halfB(whh, LH, b - 512, t, g_Bhh);
    else if (b < 1056)  conv_halfW(gcnw, b - 1024, t, g_Wg);
    else if (b < 1184)  conv_halfW(p1w, b - 1056, t, g_W1);
    else if (b < 1312)  conv_halfW(p2w, b - 1184, t, g_W2);
    else {
        int idx = (b - 1312) * 256 + t;
        size_t c4 = (size_t)idx << 2;
        if (c4 + 3 >= (size_t)NSYM * ED) {
            for (size_t c = c4; c < (size_t)NSYM * ED; c++)
                g_EmbH[c] = __float2half_rn(emb[c]);
            return;
        }
        float4 v = *(const float4*)(emb + c4);
        __half2 h01, h23;
        h01.x = __float2half_rn(v.x); h01.y = __float2half_rn(v.y);
        h23.x = __float2half_rn(v.z); h23.y = __float2half_rn(v.w);
        *(__half2*)(g_EmbH + c4)     = h01;
        *(__half2*)(g_EmbH + c4 + 2) = h23;
    }
}

// ---------------- K1: gather + sum over neighbors (fp16 table, warp-split-k) ----
__global__ __launch_bounds__(256) void k_gather(
    const int* __restrict__ qlc, const int* __restrict__ qrc,
    const int* __restrict__ slc, const int* __restrict__ src_,
    const float* __restrict__ qld, const float* __restrict__ qrd,
    const float* __restrict__ sld, const float* __restrict__ srd)
{
    __shared__ int ids[NBR * 2];
    __shared__ float red[8][128];
    int b = blockIdx.x;
    const int* conn; const float* degp; int row;
    if (b < BATCH)               { conn = qlc;  degp = qld; row = b; }
    else if (b < 2*BATCH)        { conn = qrc;  degp = qrd; row = b - BATCH; }
    else if (b < 2*BATCH + FEW)  { conn = slc;  degp = sld; row = b - 2*BATCH; }
    else                         { conn = src_; degp = srd; row = b - 2*BATCH - FEW; }
    const int* p = conn + (size_t)row * NBR * 2;
    int t = threadIdx.x;
    for (int i = t; i < NBR * 2; i += 256) ids[i] = p[i];
    if (t == 0) g_deg[b] = degp[row];
    __syncthreads();

    int w = t >> 5, lane = t & 31;
    int side = w >> 2;        // 0 = rel, 1 = ent
    int ks = w & 3;
    float4 acc = make_float4(0.f, 0.f, 0.f, 0.f);
    #pragma unroll 2
    for (int k = ks; k < NBR; k += 4) {
        int id = ids[2 * k + side];
        uint2 v = __ldg((const uint2*)(g_EmbH + (size_t)id * ED) + lane);
        __half2 h01 = *(__half2*)&v.x;
        __half2 h23 = *(__half2*)&v.y;
        acc.x += __half2float(h01.x); acc.y += __half2float(h01.y);
        acc.z += __half2float(h23.x); acc.w += __half2float(h23.y);
    }
    *(float4*)&red[w][lane * 4] = acc;
    __syncthreads();

    int s2 = t >> 7, col = t & 127;
    float a = red[s2 * 4 + 0][col] + red[s2 * 4 + 1][col]
            + red[s2 * 4 + 2][col] + red[s2 * 4 + 3][col];
    g_Sh[(size_t)b * DM + t] = __float2half_rn(a);
}

// ---------------- generic HMMA GEMM: C[M,N] = A[M,K] @ B[N,K]^T ----------------
// fp16 single-term GEMM: per k32-chunk load Ah/Bh tiles, cp.async pipeline,
// ldmatrix fragment loads, templated epilogues.
// MI = m-frags per warp (1 -> 64-row CTA tile, 2 -> 128-row).
#define SMPAD 40
#define ROWB (SMPAD * 2)          // 80 bytes per padded row
#define HSTG(MI) ((64 * (MI) + 128) * ROWB)
#define STAGES 4
#define HSM(MI) (STAGES * HSTG(MI))

template<int MODE, int KTILES, int MI>
__global__ __launch_bounds__(256, 2) void k_hmma(
    const __half* __restrict__ Ah, const __half* __restrict__ Bh,
    const float* __restrict__ e0, __half* __restrict__ Aout_h)
{
    constexpr int K = KTILES * 32;
    constexpr int nchunks = KTILES;
    constexpr int TM = 64 * MI;
    constexpr int STG = HSTG(MI);
    constexpr int offBh = TM * ROWB;

    extern __shared__ char smem[];
    uint32_t sBase = smem_u32(smem);

    int tid = threadIdx.x, lane = tid & 31, w = tid >> 5;
    int m0 = blockIdx.y * TM, n0 = blockIdx.x * 128;
    int wm = w >> 1, wn = w & 1;

    int aRow = (MI == 2) ? (tid >> 1) : (tid >> 2);
    int aSeg = (MI == 2) ? (tid & 1)  : (tid & 3);
    int bRow = tid >> 1;
    int bSeg = tid & 1;

    uint32_t aFragOff = (uint32_t)(lane & 15) * ROWB + ((lane >> 4) * 16)
                      + (uint32_t)(wm * 16 * MI) * ROWB;
    uint32_t bFragOff = (uint32_t)((lane & 7) + ((lane >> 4) * 8)) * ROWB
                      + (((lane >> 3) & 1) * 16)
                      + (uint32_t)(wn * 64) * ROWB;

    uint32_t aDst = (uint32_t)aRow * ROWB + aSeg * 16;
    uint32_t bDst = (uint32_t)bRow * ROWB + bSeg * 16;

    float acc[MI][8][4];
    #pragma unroll
    for (int i = 0; i < MI; i++)
        #pragma unroll
        for (int j = 0; j < 8; j++)
            #pragma unroll
            for (int e = 0; e < 4; e++) acc[i][j][e] = 0.f;

    auto issue = [&](int slot, int chunk) {
        int kc = chunk * 32;
        uint32_t st = sBase + slot * STG;
        const __half* Aph = Ah + (size_t)(m0 + aRow) * K + kc + aSeg * 8;
        const __half* Bph = Bh + (size_t)(n0 + bRow) * K + kc + bSeg * 8;
        if (MI == 2) {
            cpa16(st + aDst,      Aph);
            cpa16(st + aDst + 32, Aph + 16);
        } else {
            cpa16(st + aDst,      Aph);
        }
        cpa16(st + offBh + bDst,      Bph);
        cpa16(st + offBh + bDst + 32, Bph + 16);
    };

    // prologue: stages 0..STAGES-2
    #pragma unroll
    for (int s = 0; s < STAGES - 1; s++) { issue(s, s); CP_COMMIT(); }

    #pragma unroll 1
    for (int it = 0; it < nchunks; it++) {
        CP_WAIT(STAGES - 2);
        __syncthreads();
        int nxt = it + STAGES - 1;
        if (nxt < nchunks) issue(nxt % STAGES, nxt);
        CP_COMMIT();

        uint32_t st = sBase + (it % STAGES) * STG;
        #pragma unroll
        for (int ks = 0; ks < 2; ks++) {
            uint32_t abH = st + aFragOff + ks * 32;
            uint32_t bbH = st + offBh + bFragOff + ks * 32;

            uint32_t afr[MI][4];
            ldmx4(abH, afr[0][0], afr[0][1], afr[0][2], afr[0][3]);
            if (MI == 2)
                ldmx4(abH + 16 * ROWB, afr[MI-1][0], afr[MI-1][1], afr[MI-1][2], afr[MI-1][3]);

            uint32_t bfrH[8][2];
            #pragma unroll
            for (int q = 0; q < 4; q++)
                ldmx4(bbH + q * 16 * ROWB,
                      bfrH[2*q][0], bfrH[2*q][1], bfrH[2*q+1][0], bfrH[2*q+1][1]);
            #pragma unroll
            for (int nj = 0; nj < 8; nj++)
                #pragma unroll
                for (int mi = 0; mi < MI; mi++)
                    MMA(acc[mi][nj], afr[mi], bfrH[nj][0], bfrH[nj][1]);
        }
    }

    // ---------------- epilogues ----------------
    if (MODE == 2) {
        #pragma unroll
        for (int mi = 0; mi < MI; mi++) {
            int r0 = m0 + wm * 16 * MI + mi * 16 + (lane >> 2);
            #pragma unroll
            for (int rr = 0; rr < 2; rr++) {
                int gb = r0 + rr * 8;
                if (gb >= NITEMS) continue;
                float dg = g_deg[gb];
                int r2, cb;
                if (gb < BATCH)                { r2 = gb;                         cb = 0; }
                else if (gb < 2*BATCH)         { r2 = gb - BATCH;                 cb = ED; }
                else if (gb < 2*BATCH + FEW)   { r2 = BATCH + gb - 2*BATCH;       cb = 0; }
                else                           { r2 = BATCH + gb - 2*BATCH - FEW; cb = ED; }
                #pragma unroll
                for (int nj = 0; nj < 8; nj++) {
                    int cc = n0 + wn * 64 + nj * 8 + ((lane & 3) << 1);  // 0..127
                    float v0 = fast_tanh((acc[mi][nj][rr * 2 + 0] + 200.f * e0[cc])     / dg);
                    float v1 = fast_tanh((acc[mi][nj][rr * 2 + 1] + 200.f * e0[cc + 1]) / dg);
                    size_t off = (size_t)r2 * DM + cb + cc;
                    g_X32[off] = v0; g_X32[off + 1] = v1;
                    g_Xh[off]     = __float2half_rn(v0);
                    g_Xh[off + 1] = __float2half_rn(v1);
                }
            }
        }
    } else if (MODE == 3) {
        #pragma unroll
        for (int mi = 0; mi < MI; mi++) {
            int r0 = m0 + wm * 16 * MI + mi * 16 + (lane >> 2);
            #pragma unroll
            for (int rr = 0; rr < 2; rr++) {
                int mr = r0 + rr * 8;
                #pragma unroll
                for (int nj = 0; nj < 8; nj++) {
                    int cc = n0 + wn * 64 + nj * 8 + ((lane & 3) << 1);
                    float v0 = fmaxf(acc[mi][nj][rr * 2 + 0] + e0[cc], 0.f);
                    float v1 = fmaxf(acc[mi][nj][rr * 2 + 1] + e0[cc + 1], 0.f);
                    size_t off = (size_t)mr * DI + cc;
                    g_Hh[off]     = __float2half_rn(v0);
                    g_Hh[off + 1] = __float2half_rn(v1);
                }
            }
        }
    } else if (MODE == 4) {
        #pragma unroll
        for (int mi = 0; mi < MI; mi++) {
            int r0 = m0 + wm * 16 * MI + mi * 16 + (lane >> 2);
            #pragma unroll
            for (int rr = 0; rr < 2; rr++) {
                int mr = r0 + rr * 8;
                #pragma unroll
                for (int nj = 0; nj < 8; nj++) {
                    int cc = n0 + wn * 64 + nj * 8 + ((lane & 3) << 1);
                    size_t off = (size_t)mr * DM + cc;
                    float2 xr = *(const float2*)(g_X32 + off);
                    float2 o;
                    o.x = acc[mi][nj][rr * 2 + 0] + e0[cc]     + xr.x;
                    o.y = acc[mi][nj][rr * 2 + 1] + e0[cc + 1] + xr.y;
                    *(float2*)(g_out32 + off) = o;
                }
            }
        }
    } else { // MODE 5 / 6: fused LSTM gates
        constexpr bool first = (MODE == 5);
        #pragma unroll
        for (int mi = 0; mi < MI; mi++) {
            int mr = m0 + wm * 16 * MI + mi * 16 + (lane >> 2);
            #pragma unroll
            for (int nj = 0; nj < 8; nj++) {
                int cc = n0 + wn * 64 + nj * 8 + ((lane & 3) << 1);
                float d0 = acc[mi][nj][0], d1 = acc[mi][nj][1];
                float d2 = acc[mi][nj][2], d3 = acc[mi][nj][3];
                if (first) {
                    float2 bsp = *(const float2*)(g_bsump + cc);
                    d0 += bsp.x; d1 += bsp.y; d2 += bsp.x; d3 += bsp.y;
                    float2 o0; o0.x = d0; o0.y = d1;
                    float2 o1; o1.x = d2; o1.y = d3;
                    *(float2*)(g_xwp + (size_t)mr * G4 + cc) = o0;
                    *(float2*)(g_xwp + (size_t)(mr + 8) * G4 + cc) = o1;
                } else {
                    float2 sp = *(const float2*)(g_spartp + cc);
                    float2 x0 = *(const float2*)(g_xwp + (size_t)mr * G4 + cc);
                    float2 x1 = *(const float2*)(g_xwp + (size_t)(mr + 8) * G4 + cc);
                    d0 += x0.x + sp.x; d1 += x0.y + sp.y;
                    d2 += x1.x + sp.x; d3 += x1.y + sp.y;
                }
                float p0 = __shfl_xor_sync(0xffffffffu, d0, 1);
                float p1 = __shfl_xor_sync(0xffffffffu, d1, 1);
                float p2 = __shfl_xor_sync(0xffffffffu, d2, 1);
                float p3 = __shfl_xor_sync(0xffffffffu, d3, 1);
                if (((lane & 3) & 1) == 0) {
                    int u = cc >> 2;     // unit index 0..511
                    float cp0 = first ? 0.f : g_c[(size_t)mr * LH + u];
                    float cn0 = sigmoidf(d1) * cp0 + sigmoidf(d0) * fast_tanh(p0);
                    g_c[(size_t)mr * LH + u] = cn0;
                    float cp1 = first ? 0.f : g_c[(size_t)(mr + 8) * LH + u];
                    float cn1 = sigmoidf(d3) * cp1 + sigmoidf(d2) * fast_tanh(p2);
                    g_c[(size_t)(mr + 8) * LH + u] = cn1;
                    if (u < DM) {
                        float h0 = g_qg[(size_t)mr * DM + u] + sigmoidf(p1) * fast_tanh(cn0);
                        float h1 = g_qg[(size_t)(mr + 8) * DM + u] + sigmoidf(p3) * fast_tanh(cn1);
                        g_h[(size_t)mr * DM + u] = h0;
                        g_h[(size_t)(mr + 8) * DM + u] = h1;
                        Aout_h[(size_t)mr * DM + u]       = __float2half_rn(h0);
                        Aout_h[(size_t)(mr + 8) * DM + u] = __float2half_rn(h1);
                    }
                }
            }
        }
    }
}

// ---------------- K_ln: LayerNorm (ddof=1) + scatter -------
__global__ __launch_bounds__(256) void k_ln(
    const float* __restrict__ lna, const float* __restrict__ lnb)
{
    int t = threadIdx.x;
    int warp = t >> 5, lane = t & 31;
    int gr = blockIdx.x * 8 + warp;
    if (gr >= NROWS_SE) return;
    const float* x = g_out32 + (size_t)gr * DM;
    float xs[8];
    float s = 0.f;
    #pragma unroll
    for (int i = 0; i < 8; i++) { xs[i] = x[lane + i * 32]; s += xs[i]; }
    #pragma unroll
    for (int o = 16; o; o >>= 1) s += __shfl_xor_sync(0xffffffffu, s, o);
    float mu = s * (1.f / 256.f);
    float v = 0.f;
    #pragma unroll
    for (int i = 0; i < 8; i++) { float d = xs[i] - mu; v += d * d; }
    #pragma unroll
    for (int o = 16; o; o >>= 1) v += __shfl_xor_sync(0xffffffffu, v, o);
    float sigma = sqrtf(v * (1.f / 255.f));
    float inv = 1.f / (sigma + 0.001f);
    if (gr < BATCH) {
        #pragma unroll
        for (int i = 0; i < 8; i++) {
            int c = lane + i * 32;
            float val = (xs[i] - mu) * inv * lna[c] + lnb[c];
            g_qg[(size_t)gr * DM + c] = val;
            g_A0h[(size_t)gr * DM + c] = __float2half_rn(val);
        }
    } else {
        float* dst = g_sgrows + (size_t)(gr - BATCH) * DM;
        #pragma unroll
        for (int i = 0; i < 8; i++) {
            int c = lane + i * 32;
            dst[c] = (xs[i] - mu) * inv * lna[c] + lnb[c];
        }
    }
}

// ---------------- K_prep: sg mean + permuted spart + permuted bias sum --------
__global__ __launch_bounds__(256) void k_prep(
    const float* __restrict__ whh, const float* __restrict__ bih,
    const float* __restrict__ bhh)
{
    __shared__ float sg_s[DM];
    int t = threadIdx.x;
    {
        float a = 0.f;
        #pragma unroll
        for (int r = 0; r < FEW; r++) a += g_sgrows[(size_t)r * DM + t];
        a *= (1.f / (float)FEW);
        sg_s[t] = a;
        if (blockIdx.x == 0) g_sg[t] = a;
    }
    __syncthreads();
    int r = blockIdx.x * 256 + t;        // original gate-major row 0..2047
    const float* wr = whh + (size_t)r * LH + DM;
    float a = 0.f;
    for (int c = 0; c < DM; c++) a += sg_s[c] * __ldg(wr + c);
    int rp = 4 * (r & 511) + (r >> 9);
    g_spartp[rp] = a;
    g_bsump[rp] = bih[r] + bhh[r];
}

// ---------------- K8: final scores out[n] = dot(h[n], sg) ----------------
__global__ __launch_bounds__(256) void k_score(float* __restrict__ out)
{
    __shared__ float sg_s[DM];
    int t = threadIdx.x;
    if (t < DM) sg_s[t] = g_sg[t];
    __syncthreads();
    int warp = t >> 5, lane = t & 31;
    int n = blockIdx.x * 8 + warp;
    const float* h = g_h + (size_t)n * DM;
    float a = 0.f;
    #pragma unroll
    for (int c = lane; c < DM; c += 32) a += h[c] * sg_s[c];
    #pragma unroll
    for (int o = 16; o; o >>= 1) a += __shfl_xor_sync(0xffffffffu, a, o);
    if (lane == 0) out[n] = a;
}

// ---------------- launch ----------------
extern "C" void kernel_launch(void* const* d_in, const int* in_sizes, int n_in,
                              void* d_out, int out_size)
{
    const int*   qlc  = (const int*)  d_in[0];
    const float* qld  = (const float*)d_in[1];
    const int*   qrc  = (const int*)  d_in[2];
    const float* qrd  = (const float*)d_in[3];
    const int*   slc  = (const int*)  d_in[4];
    const float* sld  = (const float*)d_in[5];
    const int*   src_ = (const int*)  d_in[6];
    const float* srd  = (const float*)d_in[7];
    const float* emb  = (const float*)d_in[8];
    const float* gcnw = (const float*)d_in[9];
    const float* gcnb = (const float*)d_in[10];
    const float* p1w  = (const float*)d_in[11];
    const float* p1b  = (const float*)d_in[12];
    const float* p2w  = (const float*)d_in[13];
    const float* p2b  = (const float*)d_in[14];
    const float* lna  = (const float*)d_in[15];
    const float* lnb  = (const float*)d_in[16];
    const float* wih  = (const float*)d_in[17];
    const float* whh  = (const float*)d_in[18];
    const float* bih  = (const float*)d_in[19];
    const float* bhh  = (const float*)d_in[20];
    float* out = (float*)d_out;

    __half *wg, *w1, *w2, *sh, *xh, *hh2, *a0h, *a1h, *bihp, *bhhp;
    cudaGetSymbolAddress((void**)&wg, g_Wg);
    cudaGetSymbolAddress((void**)&w1, g_W1);
    cudaGetSymbolAddress((void**)&w2, g_W2);
    cudaGetSymbolAddress((void**)&sh, g_Sh);
    cudaGetSymbolAddress((void**)&xh, g_Xh);
    cudaGetSymbolAddress((void**)&hh2, g_Hh);
    cudaGetSymbolAddress((void**)&a0h, g_A0h);
    cudaGetSymbolAddress((void**)&a1h, g_A1h);
    cudaGetSymbolAddress((void**)&bihp, g_Bih);
    cudaGetSymbolAddress((void**)&bhhp, g_Bhh);

    cudaFuncSetAttribute(k_hmma<2, 8, 1>,  cudaFuncAttributeMaxDynamicSharedMemorySize, HSM(1));
    cudaFuncSetAttribute(k_hmma<3, 8, 1>,  cudaFuncAttributeMaxDynamicSharedMemorySize, HSM(1));
    cudaFuncSetAttribute(k_hmma<4, 16, 1>, cudaFuncAttributeMaxDynamicSharedMemorySize, HSM(1));
    cudaFuncSetAttribute(k_hmma<5, 8, 2>,  cudaFuncAttributeMaxDynamicSharedMemorySize, HSM(2));
    cudaFuncSetAttribute(k_hmma<6, 8, 2>,  cudaFuncAttributeMaxDynamicSharedMemorySize, HSM(2));

    // 0: all conversions (weights + embedding table) in one launch
    k_convAll<<<1312 + 25001, 256>>>(wih, whh, gcnw, p1w, p2w, emb);
    // 1: gather (fp16 table)
    k_gather<<<NITEMS, 256>>>(qlc, qrc, slc, src_, qld, qrd, sld, srd);
    // 2: GCN as GEMM
    k_hmma<2, 8, 1><<<dim3(1, MPAD_S / 64), 256, HSM(1)>>>(sh, wg, gcnb, nullptr);
    // 3: mlp1 (ncu captures index 3)
    k_hmma<3, 8, 1><<<dim3(4, MPAD_X / 64), 256, HSM(1)>>>(xh, w1, p1b, nullptr);
    // 4: mlp2
    k_hmma<4, 16, 1><<<dim3(2, MPAD_X / 64), 256, HSM(1)>>>(hh2, w2, p2b, nullptr);
    k_ln<<<(NROWS_SE + 7) / 8, 256>>>(lna, lnb);
    k_prep<<<G4 / 256, 256>>>(whh, bih, bhh);

    // LSTM steps with fused gate epilogues (A ping-pong A0 -> A1 -> A0 -> ...)
    k_hmma<5, 8, 2><<<dim3(16, 16), 256, HSM(2)>>>(a0h, bihp, nullptr, a1h);
    k_hmma<6, 8, 2><<<dim3(16, 16), 256, HSM(2)>>>(a1h, bhhp, nullptr, a0h);
    k_hmma<6, 8, 2><<<dim3(16, 16), 256, HSM(2)>>>(a0h, bhhp, nullptr, a1h);
    k_hmma<6, 8, 2><<<dim3(16, 16), 256, HSM(2)>>>(a1h, bhhp, nullptr, a0h);
    k_score<<<BATCH / 8, 256>>>(out);
}

// round 16
// speedup vs baseline: 1.1216x; 1.1147x over previous
#include <cuda_runtime.h>
#include <cuda_fp16.h>
#include <cstdint>
#include <math.h>

#define BATCH 2048
#define FEW 5
#define NBR 200
#define ED 128
#define DM 256
#define DI 512
#define LH 512
#define G4 2048          // 4*LSTM_HIDDEN
#define NSYM 200001
#define NITEMS (2*BATCH + 2*FEW)   // 4106
#define NROWS_SE (BATCH + FEW)     // 2053
#define MPAD_S 4224      // NITEMS padded to 128
#define MPAD_X 2176      // NROWS_SE padded to 128

// ================= scratch (device globals; zero-initialized) =========
__device__ float g_qg[(size_t)BATCH * DM];      // query_g (fp32, LSTM residual)
__device__ float g_sgrows[(size_t)FEW * DM];    // support rows post encoder
__device__ float g_sg[DM];                      // mean support
__device__ float g_spartp[G4];                  // permuted sg @ w_hh[:,256:].T
__device__ float g_bsump[G4];                   // permuted b_ih + b_hh
__device__ float g_xwp[(size_t)BATCH * G4];     // permuted q@w_ih.T + biases
__device__ float g_h[(size_t)BATCH * DM];       // h (256-dim)
__device__ float g_c[(size_t)BATCH * LH];       // cell state
__device__ float g_deg[MPAD_S];                 // degrees per item

// fp16 operands (single-term)
__device__ __half g_EmbH[(size_t)NSYM * ED];   // fp16 embedding table
__device__ __half g_Sh[(size_t)MPAD_S * DM];   // neighbor sums
__device__ __half g_Xh[(size_t)MPAD_X * DM];   // concat tanh output
__device__ float  g_X32[(size_t)MPAD_X * DM];  // fp32 X (residual)
__device__ __half g_Hh[(size_t)MPAD_X * DI];   // relu hidden
__device__ float  g_out32[(size_t)MPAD_X * DM];// pre-LN output
__device__ __half g_A0h[(size_t)BATCH * DM];   // LSTM A ping-pong buffers
__device__ __half g_A1h[(size_t)BATCH * DM];
__device__ __half g_Bih[(size_t)G4 * DM];      // permuted weights (fp16)
__device__ __half g_Bhh[(size_t)G4 * DM];
__device__ __half g_Wg[(size_t)ED * DM];
__device__ __half g_W1[(size_t)DI * DM];
__device__ __half g_W2[(size_t)DM * DI];

__device__ __forceinline__ float sigmoidf(float x) { return 1.f / (1.f + __expf(-x)); }
__device__ __forceinline__ float fast_tanh(float x) {
    float ax = fabsf(x);
    float e = __expf(-2.f * ax);
    float r = (1.f - e) / (1.f + e);
    return copysignf(r, x);
}
__device__ __forceinline__ uint32_t smem_u32(const void* p) {
    uint32_t a;
    asm("{ .reg .u64 tmp; cvta.to.shared.u64 tmp, %1; cvt.u32.u64 %0, tmp; }"
        : "=r"(a) : "l"(p));
    return a;
}
__device__ __forceinline__ void ldmx4(uint32_t addr, uint32_t& r0, uint32_t& r1,
                                      uint32_t& r2, uint32_t& r3) {
    asm volatile("ldmatrix.sync.aligned.m8n8.x4.shared.b16 {%0,%1,%2,%3}, [%4];"
        : "=r"(r0), "=r"(r1), "=r"(r2), "=r"(r3) : "r"(addr));
}
__device__ __forceinline__ void cpa16(uint32_t s, const void* g) {
    asm volatile("cp.async.cg.shared.global [%0], [%1], 16;" :: "r"(s), "l"(g));
}
#define CP_COMMIT() asm volatile("cp.async.commit_group;" ::: "memory")
#define CP_WAIT(n)  asm volatile("cp.async.wait_group %0;" :: "n"(n) : "memory")

#define MMA(acc, a, b0, b1) \
    asm volatile( \
        "mma.sync.aligned.m16n8k16.row.col.f32.f16.f16.f32 " \
        "{%0,%1,%2,%3}, {%4,%5,%6,%7}, {%8,%9}, {%0,%1,%2,%3};" \
        : "+f"((acc)[0]), "+f"((acc)[1]), "+f"((acc)[2]), "+f"((acc)[3]) \
        : "r"((a)[0]), "r"((a)[1]), "r"((a)[2]), "r"((a)[3]), \
          "r"(b0), "r"(b1))

// ---------------- conversion helpers ----------------
__device__ __forceinline__ void conv_halfB(const float* W, int ld, int blk, int t,
                                           __half* bh)
{
    int idx = blk * 256 + t;                      // 2048*64 groups of 4
    int row = idx >> 6, c4 = (idx & 63) << 2;
    int rp = 4 * (row & 511) + (row >> 9);        // gate permutation
    float4 v = *(const float4*)(W + (size_t)row * ld + c4);
    __half2 h01, h23;
    h01.x = __float2half_rn(v.x); h01.y = __float2half_rn(v.y);
    h23.x = __float2half_rn(v.z); h23.y = __float2half_rn(v.w);
    __half2* dh = (__half2*)(bh + (size_t)rp * DM + c4);
    dh[0] = h01; dh[1] = h23;
}
__device__ __forceinline__ void conv_halfW(const float* W, int blk, int t, __half* bh)
{
    int idx = blk * 256 + t;
    int c4 = idx << 2;
    float4 v = *(const float4*)(W + c4);
    __half2 h01, h23;
    h01.x = __float2half_rn(v.x); h01.y = __float2half_rn(v.y);
    h23.x = __float2half_rn(v.z); h23.y = __float2half_rn(v.w);
    *(__half2*)(bh + c4)     = h01;
    *(__half2*)(bh + c4 + 2) = h23;
}

// ---------------- K_convEmb: fp32 embedding table -> fp16 (25001 blocks) -------
__global__ __launch_bounds__(256) void k_convEmb(const float* __restrict__ emb)
{
    int idx = blockIdx.x * 256 + threadIdx.x;
    size_t c4 = (size_t)idx << 2;
    if (c4 + 3 >= (size_t)NSYM * ED) {
        for (size_t c = c4; c < (size_t)NSYM * ED; c++)
            g_EmbH[c] = __float2half_rn(emb[c]);
        return;
    }
    float4 v = *(const float4*)(emb + c4);
    __half2 h01, h23;
    h01.x = __float2half_rn(v.x); h01.y = __float2half_rn(v.y);
    h23.x = __float2half_rn(v.z); h23.y = __float2half_rn(v.w);
    *(__half2*)(g_EmbH + c4)     = h01;
    *(__half2*)(g_EmbH + c4 + 2) = h23;
}

// ---------------- K1: gather + sum over neighbors (fp16 table, warp-split-k)
// Blocks [0, NITEMS): gather. Blocks [NITEMS, NITEMS+1312): weight conversion
// (runs concurrently in the gather's L2-bound shadow).
__global__ __launch_bounds__(256) void k_gather(
    const int* __restrict__ qlc, const int* __restrict__ qrc,
    const int* __restrict__ slc, const int* __restrict__ src_,
    const float* __restrict__ qld, const float* __restrict__ qrd,
    const float* __restrict__ sld, const float* __restrict__ srd,
    const float* __restrict__ wih, const float* __restrict__ whh,
    const float* __restrict__ gcnw, const float* __restrict__ p1w,
    const float* __restrict__ p2w)
{
    __shared__ int ids[NBR * 2];
    __shared__ float red[8][128];
    int b = blockIdx.x;
    int t = threadIdx.x;

    if (b >= NITEMS) {
        int cb = b - NITEMS;
        if (cb < 512)        conv_halfB(wih, DM, cb, t, g_Bih);
        else if (cb < 1024)  conv_halfB(whh, LH, cb - 512, t, g_Bhh);
        else if (cb < 1056)  conv_halfW(gcnw, cb - 1024, t, g_Wg);
        else if (cb < 1184)  conv_halfW(p1w, cb - 1056, t, g_W1);
        else                 conv_halfW(p2w, cb - 1184, t, g_W2);
        return;
    }

    const int* conn; const float* degp; int row;
    if (b < BATCH)               { conn = qlc;  degp = qld; row = b; }
    else if (b < 2*BATCH)        { conn = qrc;  degp = qrd; row = b - BATCH; }
    else if (b < 2*BATCH + FEW)  { conn = slc;  degp = sld; row = b - 2*BATCH; }
    else                         { conn = src_; degp = srd; row = b - 2*BATCH - FEW; }
    const int* p = conn + (size_t)row * NBR * 2;
    for (int i = t; i < NBR * 2; i += 256) ids[i] = p[i];
    if (t == 0) g_deg[b] = degp[row];
    __syncthreads();

    int w = t >> 5, lane = t & 31;
    int side = w >> 2;        // 0 = rel, 1 = ent
    int ks = w & 3;
    float4 acc = make_float4(0.f, 0.f, 0.f, 0.f);
    #pragma unroll 2
    for (int k = ks; k < NBR; k += 4) {
        int id = ids[2 * k + side];
        uint2 v = __ldg((const uint2*)(g_EmbH + (size_t)id * ED) + lane);
        __half2 h01 = *(__half2*)&v.x;
        __half2 h23 = *(__half2*)&v.y;
        acc.x += __half2float(h01.x); acc.y += __half2float(h01.y);
        acc.z += __half2float(h23.x); acc.w += __half2float(h23.y);
    }
    *(float4*)&red[w][lane * 4] = acc;
    __syncthreads();

    int s2 = t >> 7, col = t & 127;
    float a = red[s2 * 4 + 0][col] + red[s2 * 4 + 1][col]
            + red[s2 * 4 + 2][col] + red[s2 * 4 + 3][col];
    g_Sh[(size_t)b * DM + t] = __float2half_rn(a);
}

// ---------------- generic HMMA GEMM: C[M,N] = A[M,K] @ B[N,K]^T ----------------
// fp16 single-term GEMM: per k32-chunk load Ah/Bh tiles, cp.async pipeline,
// ldmatrix fragment loads, templated epilogues.
// MI = m-frags per warp (1 -> 64-row CTA tile, 2 -> 128-row).
#define SMPAD 40
#define ROWB (SMPAD * 2)          // 80 bytes per padded row
#define HSTG(MI) ((64 * (MI) + 128) * ROWB)
#define STAGES 4
#define HSM(MI) (STAGES * HSTG(MI))

template<int MODE, int KTILES, int MI>
__global__ __launch_bounds__(256, 2) void k_hmma(
    const __half* __restrict__ Ah, const __half* __restrict__ Bh,
    const float* __restrict__ e0, __half* __restrict__ Aout_h)
{
    constexpr int K = KTILES * 32;
    constexpr int nchunks = KTILES;
    constexpr int TM = 64 * MI;
    constexpr int STG = HSTG(MI);
    constexpr int offBh = TM * ROWB;

    extern __shared__ char smem[];
    uint32_t sBase = smem_u32(smem);

    int tid = threadIdx.x, lane = tid & 31, w = tid >> 5;
    int m0 = blockIdx.y * TM, n0 = blockIdx.x * 128;
    int wm = w >> 1, wn = w & 1;

    int aRow = (MI == 2) ? (tid >> 1) : (tid >> 2);
    int aSeg = (MI == 2) ? (tid & 1)  : (tid & 3);
    int bRow = tid >> 1;
    int bSeg = tid & 1;

    uint32_t aFragOff = (uint32_t)(lane & 15) * ROWB + ((lane >> 4) * 16)
                      + (uint32_t)(wm * 16 * MI) * ROWB;
    uint32_t bFragOff = (uint32_t)((lane & 7) + ((lane >> 4) * 8)) * ROWB
                      + (((lane >> 3) & 1) * 16)
                      + (uint32_t)(wn * 64) * ROWB;

    uint32_t aDst = (uint32_t)aRow * ROWB + aSeg * 16;
    uint32_t bDst = (uint32_t)bRow * ROWB + bSeg * 16;

    float acc[MI][8][4];
    #pragma unroll
    for (int i = 0; i < MI; i++)
        #pragma unroll
        for (int j = 0; j < 8; j++)
            #pragma unroll
            for (int e = 0; e < 4; e++) acc[i][j][e] = 0.f;

    auto issue = [&](int slot, int chunk) {
        int kc = chunk * 32;
        uint32_t st = sBase + slot * STG;
        const __half* Aph = Ah + (size_t)(m0 + aRow) * K + kc + aSeg * 8;
        const __half* Bph = Bh + (size_t)(n0 + bRow) * K + kc + bSeg * 8;
        if (MI == 2) {
            cpa16(st + aDst,      Aph);
            cpa16(st + aDst + 32, Aph + 16);
        } else {
            cpa16(st + aDst,      Aph);
        }
        cpa16(st + offBh + bDst,      Bph);
        cpa16(st + offBh + bDst + 32, Bph + 16);
    };

    // prologue: stages 0..STAGES-2
    #pragma unroll
    for (int s = 0; s < STAGES - 1; s++) { issue(s, s); CP_COMMIT(); }

    #pragma unroll 1
    for (int it = 0; it < nchunks; it++) {
        CP_WAIT(STAGES - 2);
        __syncthreads();
        int nxt = it + STAGES - 1;
        if (nxt < nchunks) issue(nxt % STAGES, nxt);
        CP_COMMIT();

        uint32_t st = sBase + (it % STAGES) * STG;
        #pragma unroll
        for (int ks = 0; ks < 2; ks++) {
            uint32_t abH = st + aFragOff + ks * 32;
            uint32_t bbH = st + offBh + bFragOff + ks * 32;

            uint32_t afr[MI][4];
            ldmx4(abH, afr[0][0], afr[0][1], afr[0][2], afr[0][3]);
            if (MI == 2)
                ldmx4(abH + 16 * ROWB, afr[MI-1][0], afr[MI-1][1], afr[MI-1][2], afr[MI-1][3]);

            uint32_t bfrH[8][2];
            #pragma unroll
            for (int q = 0; q < 4; q++)
                ldmx4(bbH + q * 16 * ROWB,
                      bfrH[2*q][0], bfrH[2*q][1], bfrH[2*q+1][0], bfrH[2*q+1][1]);
            #pragma unroll
            for (int nj = 0; nj < 8; nj++)
                #pragma unroll
                for (int mi = 0; mi < MI; mi++)
                    MMA(acc[mi][nj], afr[mi], bfrH[nj][0], bfrH[nj][1]);
        }
    }

    // ---------------- epilogues ----------------
    if (MODE == 2) {
        #pragma unroll
        for (int mi = 0; mi < MI; mi++) {
            int r0 = m0 + wm * 16 * MI + mi * 16 + (lane >> 2);
            #pragma unroll
            for (int rr = 0; rr < 2; rr++) {
                int gb = r0 + rr * 8;
                if (gb >= NITEMS) continue;
                float dg = g_deg[gb];
                int r2, cb;
                if (gb < BATCH)                { r2 = gb;                         cb = 0; }
                else if (gb < 2*BATCH)         { r2 = gb - BATCH;                 cb = ED; }
                else if (gb < 2*BATCH + FEW)   { r2 = BATCH + gb - 2*BATCH;       cb = 0; }
                else                           { r2 = BATCH + gb - 2*BATCH - FEW; cb = ED; }
                #pragma unroll
                for (int nj = 0; nj < 8; nj++) {
                    int cc = n0 + wn * 64 + nj * 8 + ((lane & 3) << 1);  // 0..127
                    float v0 = fast_tanh((acc[mi][nj][rr * 2 + 0] + 200.f * e0[cc])     / dg);
                    float v1 = fast_tanh((acc[mi][nj][rr * 2 + 1] + 200.f * e0[cc + 1]) / dg);
                    size_t off = (size_t)r2 * DM + cb + cc;
                    g_X32[off] = v0; g_X32[off + 1] = v1;
                    g_Xh[off]     = __float2half_rn(v0);
                    g_Xh[off + 1] = __float2half_rn(v1);
                }
            }
        }
    } else if (MODE == 3) {
        #pragma unroll
        for (int mi = 0; mi < MI; mi++) {
            int r0 = m0 + wm * 16 * MI + mi * 16 + (lane >> 2);
            #pragma unroll
            for (int rr = 0; rr < 2; rr++) {
                int mr = r0 + rr * 8;
                #pragma unroll
                for (int nj = 0; nj < 8; nj++) {
                    int cc = n0 + wn * 64 + nj * 8 + ((lane & 3) << 1);
                    float v0 = fmaxf(acc[mi][nj][rr * 2 + 0] + e0[cc], 0.f);
                    float v1 = fmaxf(acc[mi][nj][rr * 2 + 1] + e0[cc + 1], 0.f);
                    size_t off = (size_t)mr * DI + cc;
                    g_Hh[off]     = __float2half_rn(v0);
                    g_Hh[off + 1] = __float2half_rn(v1);
                }
            }
        }
    } else if (MODE == 4) {
        #pragma unroll
        for (int mi = 0; mi < MI; mi++) {
            int r0 = m0 + wm * 16 * MI + mi * 16 + (lane >> 2);
            #pragma unroll
            for (int rr = 0; rr < 2; rr++) {
                int mr = r0 + rr * 8;
                #pragma unroll
                for (int nj = 0; nj < 8; nj++) {
                    int cc = n0 + wn * 64 + nj * 8 + ((lane & 3) << 1);
                    size_t off = (size_t)mr * DM + cc;
                    float2 xr = *(const float2*)(g_X32 + off);
                    float2 o;
                    o.x = acc[mi][nj][rr * 2 + 0] + e0[cc]     + xr.x;
                    o.y = acc[mi][nj][rr * 2 + 1] + e0[cc + 1] + xr.y;
                    *(float2*)(g_out32 + off) = o;
                }
            }
        }
    } else { // MODE 5 / 6: fused LSTM gates
        constexpr bool first = (MODE == 5);
        #pragma unroll
        for (int mi = 0; mi < MI; mi++) {
            int mr = m0 + wm * 16 * MI + mi * 16 + (lane >> 2);
            #pragma unroll
            for (int nj = 0; nj < 8; nj++) {
                int cc = n0 + wn * 64 + nj * 8 + ((lane & 3) << 1);
                float d0 = acc[mi][nj][0], d1 = acc[mi][nj][1];
                float d2 = acc[mi][nj][2], d3 = acc[mi][nj][3];
                if (first) {
                    float2 bsp = *(const float2*)(g_bsump + cc);
                    d0 += bsp.x; d1 += bsp.y; d2 += bsp.x; d3 += bsp.y;
                    float2 o0; o0.x = d0; o0.y = d1;
                    float2 o1; o1.x = d2; o1.y = d3;
                    *(float2*)(g_xwp + (size_t)mr * G4 + cc) = o0;
                    *(float2*)(g_xwp + (size_t)(mr + 8) * G4 + cc) = o1;
                } else {
                    float2 sp = *(const float2*)(g_spartp + cc);
                    float2 x0 = *(const float2*)(g_xwp + (size_t)mr * G4 + cc);
                    float2 x1 = *(const float2*)(g_xwp + (size_t)(mr + 8) * G4 + cc);
                    d0 += x0.x + sp.x; d1 += x0.y + sp.y;
                    d2 += x1.x + sp.x; d3 += x1.y + sp.y;
                }
                float p0 = __shfl_xor_sync(0xffffffffu, d0, 1);
                float p1 = __shfl_xor_sync(0xffffffffu, d1, 1);
                float p2 = __shfl_xor_sync(0xffffffffu, d2, 1);
                float p3 = __shfl_xor_sync(0xffffffffu, d3, 1);
                if (((lane & 3) & 1) == 0) {
                    int u = cc >> 2;     // unit index 0..511
                    float cp0 = first ? 0.f : g_c[(size_t)mr * LH + u];
                    float cn0 = sigmoidf(d1) * cp0 + sigmoidf(d0) * fast_tanh(p0);
                    g_c[(size_t)mr * LH + u] = cn0;
                    float cp1 = first ? 0.f : g_c[(size_t)(mr + 8) * LH + u];
                    float cn1 = sigmoidf(d3) * cp1 + sigmoidf(d2) * fast_tanh(p2);
                    g_c[(size_t)(mr + 8) * LH + u] = cn1;
                    if (u < DM) {
                        float h0 = g_qg[(size_t)mr * DM + u] + sigmoidf(p1) * fast_tanh(cn0);
                        float h1 = g_qg[(size_t)(mr + 8) * DM + u] + sigmoidf(p3) * fast_tanh(cn1);
                        g_h[(size_t)mr * DM + u] = h0;
                        g_h[(size_t)(mr + 8) * DM + u] = h1;
                        Aout_h[(size_t)mr * DM + u]       = __float2half_rn(h0);
                        Aout_h[(size_t)(mr + 8) * DM + u] = __float2half_rn(h1);
                    }
                }
            }
        }
    }
}

// ---------------- K_ln: LayerNorm (ddof=1) + scatter -------
__global__ __launch_bounds__(256) void k_ln(
    const float* __restrict__ lna, const float* __restrict__ lnb)
{
    int t = threadIdx.x;
    int warp = t >> 5, lane = t & 31;
    int gr = blockIdx.x * 8 + warp;
    if (gr >= NROWS_SE) return;
    const float* x = g_out32 + (size_t)gr * DM;
    float xs[8];
    float s = 0.f;
    #pragma unroll
    for (int i = 0; i < 8; i++) { xs[i] = x[lane + i * 32]; s += xs[i]; }
    #pragma unroll
    for (int o = 16; o; o >>= 1) s += __shfl_xor_sync(0xffffffffu, s, o);
    float mu = s * (1.f / 256.f);
    float v = 0.f;
    #pragma unroll
    for (int i = 0; i < 8; i++) { float d = xs[i] - mu; v += d * d; }
    #pragma unroll
    for (int o = 16; o; o >>= 1) v += __shfl_xor_sync(0xffffffffu, v, o);
    float sigma = sqrtf(v * (1.f / 255.f));
    float inv = 1.f / (sigma + 0.001f);
    if (gr < BATCH) {
        #pragma unroll
        for (int i = 0; i < 8; i++) {
            int c = lane + i * 32;
            float val = (xs[i] - mu) * inv * lna[c] + lnb[c];
            g_qg[(size_t)gr * DM + c] = val;
            g_A0h[(size_t)gr * DM + c] = __float2half_rn(val);
        }
    } else {
        float* dst = g_sgrows + (size_t)(gr - BATCH) * DM;
        #pragma unroll
        for (int i = 0; i < 8; i++) {
            int c = lane + i * 32;
            dst[c] = (xs[i] - mu) * inv * lna[c] + lnb[c];
        }
    }
}

// ---------------- K_prep: sg mean + permuted spart + permuted bias sum --------
// 4 threads per w_hh row (64-elem float4 segments), grid 32 blocks.
__global__ __launch_bounds__(256) void k_prep(
    const float* __restrict__ whh, const float* __restrict__ bih,
    const float* __restrict__ bhh)
{
    __shared__ float sg_s[DM];
    int t = threadIdx.x;
    if (t < DM) {
        float a = 0.f;
        #pragma unroll
        for (int r = 0; r < FEW; r++) a += g_sgrows[(size_t)r * DM + t];
        a *= (1.f / (float)FEW);
        sg_s[t] = a;
        if (blockIdx.x == 0) g_sg[t] = a;
    }
    __syncthreads();
    int r = blockIdx.x * 64 + (t >> 2);  // gate-major row 0..2047
    int seg = t & 3;                     // 64-elem segment
    const float4* wr = (const float4*)(whh + (size_t)r * LH + DM + seg * 64);
    const float4* sg4 = (const float4*)(sg_s + seg * 64);
    float a = 0.f;
    #pragma unroll
    for (int c = 0; c < 16; c++) {
        float4 wv = __ldg(wr + c);
        float4 sv = sg4[c];
        a += wv.x * sv.x + wv.y * sv.y + wv.z * sv.z + wv.w * sv.w;
    }
    a += __shfl_xor_sync(0xffffffffu, a, 1);
    a += __shfl_xor_sync(0xffffffffu, a, 2);
    if (seg == 0) {
        int rp = 4 * (r & 511) + (r >> 9);
        g_spartp[rp] = a;
        g_bsump[rp] = bih[r] + bhh[r];
    }
}

// ---------------- K8: final scores out[n] = dot(h[n], sg) ----------------
__global__ __launch_bounds__(256) void k_score(float* __restrict__ out)
{
    __shared__ float sg_s[DM];
    int t = threadIdx.x;
    if (t < DM) sg_s[t] = g_sg[t];
    __syncthreads();
    int warp = t >> 5, lane = t & 31;
    int n = blockIdx.x * 8 + warp;
    const float* h = g_h + (size_t)n * DM;
    float a = 0.f;
    #pragma unroll
    for (int c = lane; c < DM; c += 32) a += h[c] * sg_s[c];
    #pragma unroll
    for (int o = 16; o; o >>= 1) a += __shfl_xor_sync(0xffffffffu, a, o);
    if (lane == 0) out[n] = a;
}

// ---------------- launch ----------------
extern "C" void kernel_launch(void* const* d_in, const int* in_sizes, int n_in,
                              void* d_out, int out_size)
{
    const int*   qlc  = (const int*)  d_in[0];
    const float* qld  = (const float*)d_in[1];
    const int*   qrc  = (const int*)  d_in[2];
    const float* qrd  = (const float*)d_in[3];
    const int*   slc  = (const int*)  d_in[4];
    const float* sld  = (const float*)d_in[5];
    const int*   src_ = (const int*)  d_in[6];
    const float* srd  = (const float*)d_in[7];
    const float* emb  = (const float*)d_in[8];
    const float* gcnw = (const float*)d_in[9];
    const float* gcnb = (const float*)d_in[10];
    const float* p1w  = (const float*)d_in[11];
    const float* p1b  = (const float*)d_in[12];
    const float* p2w  = (const float*)d_in[13];
    const float* p2b  = (const float*)d_in[14];
    const float* lna  = (const float*)d_in[15];
    const float* lnb  = (const float*)d_in[16];
    const float* wih  = (const float*)d_in[17];
    const float* whh  = (const float*)d_in[18];
    const float* bih  = (const float*)d_in[19];
    const float* bhh  = (const float*)d_in[20];
    float* out = (float*)d_out;

    __half *wg, *w1, *w2, *sh, *xh, *hh2, *a0h, *a1h, *bihp, *bhhp;
    cudaGetSymbolAddress((void**)&wg, g_Wg);
    cudaGetSymbolAddress((void**)&w1, g_W1);
    cudaGetSymbolAddress((void**)&w2, g_W2);
    cudaGetSymbolAddress((void**)&sh, g_Sh);
    cudaGetSymbolAddress((void**)&xh, g_Xh);
    cudaGetSymbolAddress((void**)&hh2, g_Hh);
    cudaGetSymbolAddress((void**)&a0h, g_A0h);
    cudaGetSymbolAddress((void**)&a1h, g_A1h);
    cudaGetSymbolAddress((void**)&bihp, g_Bih);
    cudaGetSymbolAddress((void**)&bhhp, g_Bhh);

    cudaFuncSetAttribute(k_hmma<2, 8, 1>,  cudaFuncAttributeMaxDynamicSharedMemorySize, HSM(1));
    cudaFuncSetAttribute(k_hmma<3, 8, 1>,  cudaFuncAttributeMaxDynamicSharedMemorySize, HSM(1));
    cudaFuncSetAttribute(k_hmma<4, 16, 1>, cudaFuncAttributeMaxDynamicSharedMemorySize, HSM(1));
    cudaFuncSetAttribute(k_hmma<5, 8, 2>,  cudaFuncAttributeMaxDynamicSharedMemorySize, HSM(2));
    cudaFuncSetAttribute(k_hmma<6, 8, 2>,  cudaFuncAttributeMaxDynamicSharedMemorySize, HSM(2));

    // 0: embedding table -> fp16
    k_convEmb<<<25001, 256>>>(emb);
    // 1: gather + weight conversion (conv blocks ride in the gather's shadow)
    k_gather<<<NITEMS + 1312, 256>>>(qlc, qrc, slc, src_, qld, qrd, sld, srd,
                                     wih, whh, gcnw, p1w, p2w);
    // 2: GCN as GEMM
    k_hmma<2, 8, 1><<<dim3(1, MPAD_S / 64), 256, HSM(1)>>>(sh, wg, gcnb, nullptr);
    // 3: mlp1 (ncu captures index 3)
    k_hmma<3, 8, 1><<<dim3(4, MPAD_X / 64), 256, HSM(1)>>>(xh, w1, p1b, nullptr);
    // 4: mlp2
    k_hmma<4, 16, 1><<<dim3(2, MPAD_X / 64), 256, HSM(1)>>>(hh2, w2, p2b, nullptr);
    k_ln<<<(NROWS_SE + 7) / 8, 256>>>(lna, lnb);
    k_prep<<<32, 256>>>(whh, bih, bhh);

    // LSTM steps with fused gate epilogues (A ping-pong A0 -> A1 -> A0 -> ...)
    k_hmma<5, 8, 2><<<dim3(16, 16), 256, HSM(2)>>>(a0h, bihp, nullptr, a1h);
    k_hmma<6, 8, 2><<<dim3(16, 16), 256, HSM(2)>>>(a1h, bhhp, nullptr, a0h);
    k_hmma<6, 8, 2><<<dim3(16, 16), 256, HSM(2)>>>(a0h, bhhp, nullptr, a1h);
    k_hmma<6, 8, 2><<<dim3(16, 16), 256, HSM(2)>>>(a1h, bhhp, nullptr, a0h);
    k_score<<<BATCH / 8, 256>>>(out);
}